// round 15
// baseline (speedup 1.0000x reference)
#include <cuda_runtime.h>
#include <cuda_fp16.h>
#include <math.h>

#define D 128
#define NMAX 50000
#define EMAX 640000
#define DEC_ROWS 32

// ---------------- scratch globals ------------------------------------------------
__device__ __align__(16) float g_prevA[NMAX * D];
__device__ __align__(16) float g_prevB[NMAX * D];
__device__ __align__(16) float g_hsum[NMAX * D];
__device__ __align__(16) float g_y0[NMAX * (D / 2)];
__device__ __align__(16) float g_stats[2 * D + 2 * (D / 2)];
__device__ __align__(16) float g_WTd[D * (D / 2)];
__device__ __align__(16) float g_bias[512];
// B fragments (single fp16): [mat(6: hf*3+gate)][ntile(16)][kstep(8)][lane(32)] -> uint2 {b0,b1}
__device__ __align__(16) uint2 g_Bfrag[6 * 4096];
// CSR-by-dst
__device__ __align__(16) int  g_deg[NMAX];
__device__ __align__(16) int  g_off[NMAX + 1];
__device__ __align__(16) int  g_pos[NMAX];
__device__ __align__(16) uint2 g_edge[EMAX];   // {src, norm_bits}

__device__ __forceinline__ unsigned pack_hi_lo_f16(float x0, float x1, unsigned& lop) {
    __half h0 = __float2half_rn(x0), h1 = __float2half_rn(x1);
    float l0 = x0 - __half2float(h0), l1 = x1 - __half2float(h1);
    __half g0 = __float2half_rn(l0), g1 = __float2half_rn(l1);
    lop = ((unsigned)__half_as_ushort(g1) << 16) | __half_as_ushort(g0);
    return ((unsigned)__half_as_ushort(h1) << 16) | __half_as_ushort(h0);
}

__device__ __forceinline__ void mma16816(float* c, const unsigned* a, unsigned b0, unsigned b1) {
    asm("mma.sync.aligned.m16n8k16.row.col.f32.f16.f16.f32 "
        "{%0,%1,%2,%3}, {%4,%5,%6,%7}, {%8,%9}, {%0,%1,%2,%3};"
        : "+f"(c[0]), "+f"(c[1]), "+f"(c[2]), "+f"(c[3])
        : "r"(a[0]), "r"(a[1]), "r"(a[2]), "r"(a[3]), "r"(b0), "r"(b1));
}

// fp16-accumulate variant (2 packed-half2 accumulators)
__device__ __forceinline__ void mma16816h(unsigned* c, const unsigned* a, unsigned b0, unsigned b1) {
    asm("mma.sync.aligned.m16n8k16.row.col.f16.f16.f16.f16 "
        "{%0,%1}, {%2,%3,%4,%5}, {%6,%7}, {%0,%1};"
        : "+r"(c[0]), "+r"(c[1])
        : "r"(a[0]), "r"(a[1]), "r"(a[2]), "r"(a[3]), "r"(b0), "r"(b1));
}

__device__ __forceinline__ float fast_sigmoid(float x) {
    return __fdividef(1.f, 1.f + __expf(-x));
}
__device__ __forceinline__ float fast_tanh(float x) {
    float e = __expf(2.f * x);
    return 1.f - __fdividef(2.f, e + 1.f);
}

// ---------------- prep ------------------------------------------------------------
__global__ void prep_kernel(const float* __restrict__ Wih, const float* __restrict__ Whh,
                            const float* __restrict__ bih, const float* __restrict__ bhh,
                            const float* __restrict__ Wdec, int N) {
    int i = blockIdx.x * blockDim.x + threadIdx.x;
    int stride = gridDim.x * blockDim.x;
    if (i < 384) g_stats[i] = 0.f;
    if (i < 256) g_bias[i] = bih[i] + bhh[i];
    else if (i < 384) g_bias[i] = bih[i];
    if (i >= 384 && i < 512) g_bias[i] = bhh[i - 128];
    for (int idx = i; idx < N; idx += stride) g_deg[idx] = 0;
    for (int idx = i; idx < D * (D / 2); idx += stride) {
        int k = idx / (D / 2), j = idx % (D / 2);
        g_WTd[idx] = Wdec[j * D + k];
    }
    for (int f = i; f < 6 * 4096; f += stride) {
        int lane = f & 31;
        int ks = (f >> 5) & 7;
        int nt = (f >> 8) & 15;
        int mat = f >> 12;
        int hf = mat / 3, gate = mat % 3;
        int gg = lane >> 2, tg = lane & 3;
        int n_local = nt * 8 + gg;
        int k0 = ks * 16 + tg * 2;
        const float* W = hf ? Whh : Wih;
        const float* row = W + (size_t)(gate * 128 + n_local) * D;
        __half a0 = __float2half_rn(row[k0]);
        __half a1 = __float2half_rn(row[k0 + 1]);
        __half a2 = __float2half_rn(row[k0 + 8]);
        __half a3 = __float2half_rn(row[k0 + 9]);
        unsigned w0 = ((unsigned)__half_as_ushort(a1) << 16) | __half_as_ushort(a0);
        unsigned w1 = ((unsigned)__half_as_ushort(a3) << 16) | __half_as_ushort(a2);
        g_Bfrag[f] = make_uint2(w0, w1);
    }
}

// ---------------- CSR build --------------------------------------------------------
__global__ void count_kernel(const int* __restrict__ ei, int E) {
    int i = blockIdx.x * blockDim.x + threadIdx.x;
    if (i < E) atomicAdd(&g_deg[ei[E + i]], 1);
}

__global__ void __launch_bounds__(1024) scan_kernel(int N) {
    __shared__ int s[1024];
    int tid = threadIdx.x;
    int chunk = (N + 1023) / 1024;
    int start = tid * chunk;
    int end = min(start + chunk, N);
    int sum = 0;
    for (int i = start; i < end; i++) sum += g_deg[i];
    s[tid] = sum;
    __syncthreads();
    for (int off = 1; off < 1024; off <<= 1) {
        int v = (tid >= off) ? s[tid - off] : 0;
        __syncthreads();
        s[tid] += v;
        __syncthreads();
    }
    int run = (tid == 0) ? 0 : s[tid - 1];
    for (int i = start; i < end; i++) {
        g_off[i] = run;
        g_pos[i] = run;
        run += g_deg[i];
    }
    if (end == N && start <= N) g_off[N] = run;
}

__global__ void fill_kernel(const int* __restrict__ ei, const float* __restrict__ norm, int E) {
    int i = blockIdx.x * blockDim.x + threadIdx.x;
    if (i < E) {
        int t = ei[E + i];
        int p = atomicAdd(&g_pos[t], 1);
        g_edge[p] = make_uint2((unsigned)ei[i], __float_as_uint(norm[i]));
    }
}

// ---------------- encoder (64 rows per block) ----------------------------------------
__global__ void enc_stats_kernel(const float* __restrict__ x, const float* __restrict__ Wenc, int N) {
    int d = threadIdx.x;
    float w0 = Wenc[d * 3], w1 = Wenc[d * 3 + 1], w2 = Wenc[d * 3 + 2];
    int n0 = blockIdx.x * 64, lim = min(64, N - n0);
    float s = 0.f, sq = 0.f;
    for (int r = 0; r < lim; r++) {
        int n = n0 + r;
        float h = fmaf(x[n * 3], w0, fmaf(x[n * 3 + 1], w1, x[n * 3 + 2] * w2));
        s += h; sq += h * h;
    }
    atomicAdd(&g_stats[d], s);
    atomicAdd(&g_stats[D + d], sq);
}
__global__ void enc_apply_kernel(const float* __restrict__ x, const float* __restrict__ Wenc,
                                 const float* __restrict__ gamma, const float* __restrict__ beta, int N) {
    int d = threadIdx.x;
    float w0 = Wenc[d * 3], w1 = Wenc[d * 3 + 1], w2 = Wenc[d * 3 + 2];
    float invN = 1.f / (float)N;
    float mu = g_stats[d] * invN;
    float var = g_stats[D + d] * invN - mu * mu;
    float rs = rsqrtf(var + 1e-5f);
    float ga = gamma[d] * rs, be = beta[d] - mu * ga;
    int n0 = blockIdx.x * 64, lim = min(64, N - n0);
    for (int r = 0; r < lim; r++) {
        int n = n0 + r;
        float h = fmaf(x[n * 3], w0, fmaf(x[n * 3 + 1], w1, x[n * 3 + 2] * w2));
        float v = fmaf(h, ga, be);
        v = v > 0.f ? v : 0.f;
        g_prevA[(size_t)n * D + d] = v;
        g_hsum[(size_t)n * D + d] = v;
    }
}

// ---------------- fused layer: gather + GRU, hi f32-accum + lo f16-accum, 3 CTAs/SM ---
#define PITCH 68
#define GROWS 64
#define ABUF  (GROWS * PITCH)
#define GRU_SMEM (4 * ABUF * 4 + 512 * 4)

__global__ void __launch_bounds__(256, 3) layer_kernel(const float* __restrict__ prev_in,
                                                       float* __restrict__ prev_out, int N) {
    extern __shared__ unsigned char smraw[];
    unsigned* sA = (unsigned*)smraw;
    float* sbias = (float*)(smraw + 4 * ABUF * 4);
    int tid = threadIdx.x;
    int n0 = blockIdx.x * GROWS;
    int lane = tid & 31, wid = tid >> 5;

#pragma unroll
    for (int t = 0; t < 2; t++) sbias[t * 256 + tid] = g_bias[t * 256 + tid];

    // --- fused gather + convert: warp w handles rows [w*8, w*8+8); reads prev_in only ---
    const float4* prev4 = (const float4*)prev_in;
#pragma unroll 1
    for (int rr = 0; rr < 8; rr++) {
        int rloc = wid * 8 + rr;
        int row = n0 + rloc;
        float4 acc = make_float4(0.f, 0.f, 0.f, 0.f);
        float4 hv = make_float4(0.f, 0.f, 0.f, 0.f);
        if (row < N) {
            int beg = g_off[row], end = g_off[row + 1];
            int j = beg;
            for (; j + 3 < end; j += 4) {
                uint2 e0 = g_edge[j], e1 = g_edge[j + 1], e2 = g_edge[j + 2], e3 = g_edge[j + 3];
                float4 v0 = prev4[(size_t)e0.x * 32 + lane];
                float4 v1 = prev4[(size_t)e1.x * 32 + lane];
                float4 v2 = prev4[(size_t)e2.x * 32 + lane];
                float4 v3 = prev4[(size_t)e3.x * 32 + lane];
                float n0v = __uint_as_float(e0.y), n1v = __uint_as_float(e1.y);
                float n2v = __uint_as_float(e2.y), n3v = __uint_as_float(e3.y);
                acc.x = fmaf(n0v, v0.x, fmaf(n1v, v1.x, fmaf(n2v, v2.x, fmaf(n3v, v3.x, acc.x))));
                acc.y = fmaf(n0v, v0.y, fmaf(n1v, v1.y, fmaf(n2v, v2.y, fmaf(n3v, v3.y, acc.y))));
                acc.z = fmaf(n0v, v0.z, fmaf(n1v, v1.z, fmaf(n2v, v2.z, fmaf(n3v, v3.z, acc.z))));
                acc.w = fmaf(n0v, v0.w, fmaf(n1v, v1.w, fmaf(n2v, v2.w, fmaf(n3v, v3.w, acc.w))));
            }
            for (; j < end; j++) {
                uint2 e0 = g_edge[j];
                float4 v0 = prev4[(size_t)e0.x * 32 + lane];
                float nv = __uint_as_float(e0.y);
                acc.x = fmaf(nv, v0.x, acc.x);
                acc.y = fmaf(nv, v0.y, acc.y);
                acc.z = fmaf(nv, v0.z, acc.z);
                acc.w = fmaf(nv, v0.w, acc.w);
            }
            hv = prev4[(size_t)row * 32 + lane];
            float4 sv = ((const float4*)g_hsum)[(size_t)row * 32 + lane];
            ((float4*)g_hsum)[(size_t)row * 32 + lane] =
                make_float4(sv.x + acc.x, sv.y + acc.y, sv.z + acc.z, sv.w + acc.w);
        }
        unsigned base = rloc * PITCH + lane * 2;
        unsigned lo, hi;
        hi = pack_hi_lo_f16(acc.x, acc.y, lo);
        sA[base] = hi; sA[ABUF + base] = lo;
        hi = pack_hi_lo_f16(acc.z, acc.w, lo);
        sA[base + 1] = hi; sA[ABUF + base + 1] = lo;
        hi = pack_hi_lo_f16(hv.x, hv.y, lo);
        sA[2 * ABUF + base] = hi; sA[3 * ABUF + base] = lo;
        hi = pack_hi_lo_f16(hv.z, hv.w, lo);
        sA[2 * ABUF + base + 1] = hi; sA[3 * ABUF + base + 1] = lo;
    }
    __syncthreads();

    int gg = lane >> 2, tg = lane & 3;
    int m0 = (wid & 3) * 16;
    int cg = wid >> 2;               // col group: chunks [cg*4, cg*4+4)
    const uint2* Bf = g_Bfrag;

#pragma unroll 1
    for (int ci = 0; ci < 4; ci++) {
        int chunk = cg * 4 + ci;     // 16 d-cols per chunk
        float aR[2][4], aZ[2][4], aN[2][4], aH[2][4];
        unsigned lR[2][2], lZ[2][2], lN[2][2], lH[2][2];   // fp16-accum lo-term
#pragma unroll
        for (int nt = 0; nt < 2; nt++) {
#pragma unroll
            for (int q = 0; q < 4; q++) { aR[nt][q] = 0.f; aZ[nt][q] = 0.f; aN[nt][q] = 0.f; aH[nt][q] = 0.f; }
#pragma unroll
            for (int q = 0; q < 2; q++) { lR[nt][q] = 0u; lZ[nt][q] = 0u; lN[nt][q] = 0u; lH[nt][q] = 0u; }
        }

#pragma unroll
        for (int hf = 0; hf < 2; hf++) {
            int bh_ = (hf * 2) * ABUF;
            int bl_ = (hf * 2 + 1) * ABUF;
#pragma unroll 2
            for (int ks = 0; ks < 8; ks++) {
                int kw = ks * 8 + tg;
                int rr = m0 + gg;
                unsigned Ah[4], Al[4];
                Ah[0] = sA[bh_ + rr * PITCH + kw];
                Ah[1] = sA[bh_ + (rr + 8) * PITCH + kw];
                Ah[2] = sA[bh_ + rr * PITCH + kw + 4];
                Ah[3] = sA[bh_ + (rr + 8) * PITCH + kw + 4];
                Al[0] = sA[bl_ + rr * PITCH + kw];
                Al[1] = sA[bl_ + (rr + 8) * PITCH + kw];
                Al[2] = sA[bl_ + rr * PITCH + kw + 4];
                Al[3] = sA[bl_ + (rr + 8) * PITCH + kw + 4];
                const uint2* bp = Bf + hf * 3 * 4096 + (chunk * 2) * 256 + ks * 32 + lane;
                uint2 b00 = bp[0 * 4096 + 0 * 256];
                uint2 b01 = bp[1 * 4096 + 0 * 256];
                uint2 b02 = bp[2 * 4096 + 0 * 256];
                uint2 b10 = bp[0 * 4096 + 1 * 256];
                uint2 b11 = bp[1 * 4096 + 1 * 256];
                uint2 b12 = bp[2 * 4096 + 1 * 256];
                float (*AN_)[4] = hf ? aH : aN;
                unsigned (*LN_)[2] = hf ? lH : lN;
                // hi-term: f32 accumulate
                mma16816(aR[0], Ah, b00.x, b00.y);
                mma16816(aZ[0], Ah, b01.x, b01.y);
                mma16816(AN_[0], Ah, b02.x, b02.y);
                mma16816(aR[1], Ah, b10.x, b10.y);
                mma16816(aZ[1], Ah, b11.x, b11.y);
                mma16816(AN_[1], Ah, b12.x, b12.y);
                // lo-term (small correction): f16 accumulate
                mma16816h(lR[0], Al, b00.x, b00.y);
                mma16816h(lZ[0], Al, b01.x, b01.y);
                mma16816h(LN_[0], Al, b02.x, b02.y);
                mma16816h(lR[1], Al, b10.x, b10.y);
                mma16816h(lZ[1], Al, b11.x, b11.y);
                mma16816h(LN_[1], Al, b12.x, b12.y);
            }
        }

        // epilogue for this chunk's 16 columns
#pragma unroll
        for (int nt = 0; nt < 2; nt++) {
#pragma unroll
            for (int rh = 0; rh < 2; rh++) {
                int rloc = m0 + rh * 8 + gg;
                int row = n0 + rloc;
                if (row < N) {
                    int col = chunk * 16 + nt * 8 + tg * 2;
                    int i0 = rh * 2;
                    float2 loR = __half22float2(*(__half2*)&lR[nt][rh]);
                    float2 loZ = __half22float2(*(__half2*)&lZ[nt][rh]);
                    float2 loN = __half22float2(*(__half2*)&lN[nt][rh]);
                    float2 loH = __half22float2(*(__half2*)&lH[nt][rh]);
                    float rv0 = aR[nt][i0]     + loR.x + sbias[col];
                    float rv1 = aR[nt][i0 + 1] + loR.y + sbias[col + 1];
                    float zv0 = aZ[nt][i0]     + loZ.x + sbias[128 + col];
                    float zv1 = aZ[nt][i0 + 1] + loZ.y + sbias[128 + col + 1];
                    float in0 = aN[nt][i0]     + loN.x + sbias[256 + col];
                    float in1 = aN[nt][i0 + 1] + loN.y + sbias[256 + col + 1];
                    float hn0 = aH[nt][i0]     + loH.x + sbias[384 + col];
                    float hn1 = aH[nt][i0 + 1] + loH.y + sbias[384 + col + 1];
                    int cw = col >> 1;
                    unsigned wh = sA[2 * ABUF + rloc * PITCH + cw];
                    unsigned wl = sA[3 * ABUF + rloc * PITCH + cw];
                    float2 fh = __half22float2(*(__half2*)&wh);
                    float2 fl = __half22float2(*(__half2*)&wl);
                    float hp0 = fh.x + fl.x, hp1 = fh.y + fl.y;
                    float rg0 = fast_sigmoid(rv0);
                    float rg1 = fast_sigmoid(rv1);
                    float zg0 = fast_sigmoid(zv0);
                    float zg1 = fast_sigmoid(zv1);
                    float ng0 = fast_tanh(fmaf(rg0, hn0, in0));
                    float ng1 = fast_tanh(fmaf(rg1, hn1, in1));
                    float o0 = fmaf(zg0, hp0 - ng0, ng0);
                    float o1 = fmaf(zg1, hp1 - ng1, ng1);
                    *(float2*)(prev_out + (size_t)row * D + col) = make_float2(o0, o1);
                }
            }
        }
    }
}

// ---------------- decode (128 threads: two 16-row halves) -----------------------------
__global__ void __launch_bounds__(128) dec1_kernel(int N) {
    __shared__ float s_z[DEC_ROWS * D];
    int tid = threadIdx.x;
    int j = tid & 63;
    int half = tid >> 6;
    int n0 = blockIdx.x * DEC_ROWS;
    const float inv6 = 1.f / 6.f;
    for (int i = tid; i < DEC_ROWS * D; i += 128) {
        int n = n0 + i / D;
        s_z[i] = (n < N) ? g_hsum[(size_t)n0 * D + i] * inv6 : 0.f;
    }
    __syncthreads();
    float acc[16];
#pragma unroll
    for (int r = 0; r < 16; r++) acc[r] = 0.f;
    int r0 = half * 16;
#pragma unroll 2
    for (int k = 0; k < D; k++) {
        float w = g_WTd[k * (D / 2) + j];
#pragma unroll
        for (int r = 0; r < 16; r++) acc[r] = fmaf(w, s_z[(r0 + r) * D + k], acc[r]);
    }
    float s = 0.f, sq = 0.f;
#pragma unroll
    for (int r = 0; r < 16; r++) {
        int n = n0 + r0 + r;
        if (n < N) {
            g_y0[(size_t)n * (D / 2) + j] = acc[r];
            s += acc[r]; sq += acc[r] * acc[r];
        }
    }
    atomicAdd(&g_stats[2 * D + j], s);
    atomicAdd(&g_stats[2 * D + (D / 2) + j], sq);
}

__global__ void dec2_kernel(const float* __restrict__ gamma, const float* __restrict__ beta,
                            const float* __restrict__ W2, float* __restrict__ out, int N) {
    int warp = (blockIdx.x * blockDim.x + threadIdx.x) >> 5;
    int lane = threadIdx.x & 31;
    if (warp >= N) return;
    float invN = 1.f / (float)N;
    float acc = 0.f;
#pragma unroll
    for (int t = 0; t < 2; t++) {
        int jj = lane + t * 32;
        float mu = g_stats[2 * D + jj] * invN;
        float var = g_stats[2 * D + (D / 2) + jj] * invN - mu * mu;
        float rs = rsqrtf(var + 1e-5f);
        float v = (g_y0[(size_t)warp * (D / 2) + jj] - mu) * rs * gamma[jj] + beta[jj];
        v = v > 0.f ? v : 0.f;
        acc = fmaf(v, W2[jj], acc);
    }
#pragma unroll
    for (int o = 16; o > 0; o >>= 1) acc += __shfl_down_sync(0xffffffffu, acc, o);
    if (lane == 0) out[warp] = acc;
}

// ---------------- launch ----------------------------------------------------------------
extern "C" void kernel_launch(void* const* d_in, const int* in_sizes, int n_in,
                              void* d_out, int out_size) {
    const float* x    = (const float*)d_in[0];
    const int*   ei   = (const int*)d_in[1];
    const float* norm = (const float*)d_in[2];
    const float* Wenc = (const float*)d_in[3];
    const float* beg  = (const float*)d_in[4];
    const float* beb  = (const float*)d_in[5];
    const float* Wih  = (const float*)d_in[6];
    const float* Whh  = (const float*)d_in[7];
    const float* bih  = (const float*)d_in[8];
    const float* bhh  = (const float*)d_in[9];
    const float* Wdec = (const float*)d_in[10];
    const float* bdg  = (const float*)d_in[11];
    const float* bdb  = (const float*)d_in[12];
    const float* W2   = (const float*)d_in[13];

    int N = in_sizes[0] / 3;
    int E = in_sizes[2];
    float* out = (float*)d_out;

    cudaFuncSetAttribute(layer_kernel, cudaFuncAttributeMaxDynamicSharedMemorySize, GRU_SMEM);

    prep_kernel<<<192, 256>>>(Wih, Whh, bih, bhh, Wdec, N);
    count_kernel<<<(E + 255) / 256, 256>>>(ei, E);
    scan_kernel<<<1, 1024>>>(N);
    fill_kernel<<<(E + 255) / 256, 256>>>(ei, norm, E);

    int nb64 = (N + 63) / 64;
    enc_stats_kernel<<<nb64, 128>>>(x, Wenc, N);
    enc_apply_kernel<<<nb64, 128>>>(x, Wenc, beg, beb, N);

    float* pA = nullptr;
    float* pB = nullptr;
    cudaGetSymbolAddress((void**)&pA, g_prevA);
    cudaGetSymbolAddress((void**)&pB, g_prevB);

    int gb = (N + GROWS - 1) / GROWS;
    for (int L = 0; L < 5; L++) {
        const float* pin  = (L & 1) ? pB : pA;
        float*       pout = (L & 1) ? pA : pB;
        layer_kernel<<<gb, 256, GRU_SMEM>>>(pin, pout, N);
    }

    dec1_kernel<<<(N + DEC_ROWS - 1) / DEC_ROWS, 128>>>(N);

    long long d2threads = (long long)N * 32;
    dec2_kernel<<<(int)((d2threads + 255) / 256), 256>>>(bdg, bdb, W2, out, N);
}

// round 16
// speedup vs baseline: 1.0464x; 1.0464x over previous
#include <cuda_runtime.h>
#include <cuda_fp16.h>
#include <math.h>

#define D 128
#define NMAX 50000
#define EMAX 640000
#define DEC_ROWS 32

// ---------------- scratch globals ------------------------------------------------
__device__ __align__(16) float g_prevA[NMAX * D];
__device__ __align__(16) float g_prevB[NMAX * D];
__device__ __align__(16) float g_hsum[NMAX * D];
__device__ __align__(16) float g_y0[NMAX * (D / 2)];
__device__ __align__(16) float g_stats[2 * D + 2 * (D / 2)];
__device__ __align__(16) float g_WTd[D * (D / 2)];
__device__ __align__(16) float g_bias[512];
// B fragments (single fp16): [mat(6: hf*3+gate)][ntile(16)][kstep(8)][lane(32)] -> uint2 {b0,b1}
__device__ __align__(16) uint2 g_Bfrag[6 * 4096];
// CSR-by-dst
__device__ __align__(16) int  g_deg[NMAX];
__device__ __align__(16) int  g_off[NMAX + 1];
__device__ __align__(16) int  g_pos[NMAX];
__device__ __align__(16) uint2 g_edge[EMAX];   // {src, norm_bits}

__device__ __forceinline__ unsigned pack_hi_lo_f16(float x0, float x1, unsigned& lop) {
    __half h0 = __float2half_rn(x0), h1 = __float2half_rn(x1);
    float l0 = x0 - __half2float(h0), l1 = x1 - __half2float(h1);
    __half g0 = __float2half_rn(l0), g1 = __float2half_rn(l1);
    lop = ((unsigned)__half_as_ushort(g1) << 16) | __half_as_ushort(g0);
    return ((unsigned)__half_as_ushort(h1) << 16) | __half_as_ushort(h0);
}

__device__ __forceinline__ void mma16816(float* c, const unsigned* a, unsigned b0, unsigned b1) {
    asm("mma.sync.aligned.m16n8k16.row.col.f32.f16.f16.f32 "
        "{%0,%1,%2,%3}, {%4,%5,%6,%7}, {%8,%9}, {%0,%1,%2,%3};"
        : "+f"(c[0]), "+f"(c[1]), "+f"(c[2]), "+f"(c[3])
        : "r"(a[0]), "r"(a[1]), "r"(a[2]), "r"(a[3]), "r"(b0), "r"(b1));
}

__device__ __forceinline__ float fast_sigmoid(float x) {
    return __fdividef(1.f, 1.f + __expf(-x));
}
__device__ __forceinline__ float fast_tanh(float x) {
    float e = __expf(2.f * x);
    return 1.f - __fdividef(2.f, e + 1.f);
}

// ---------------- prep ------------------------------------------------------------
__global__ void prep_kernel(const float* __restrict__ Wih, const float* __restrict__ Whh,
                            const float* __restrict__ bih, const float* __restrict__ bhh,
                            const float* __restrict__ Wdec, int N) {
    int i = blockIdx.x * blockDim.x + threadIdx.x;
    int stride = gridDim.x * blockDim.x;
    if (i < 384) g_stats[i] = 0.f;
    if (i < 256) g_bias[i] = bih[i] + bhh[i];
    else if (i < 384) g_bias[i] = bih[i];
    if (i >= 384 && i < 512) g_bias[i] = bhh[i - 128];
    for (int idx = i; idx < N; idx += stride) g_deg[idx] = 0;
    for (int idx = i; idx < D * (D / 2); idx += stride) {
        int k = idx / (D / 2), j = idx % (D / 2);
        g_WTd[idx] = Wdec[j * D + k];
    }
    for (int f = i; f < 6 * 4096; f += stride) {
        int lane = f & 31;
        int ks = (f >> 5) & 7;
        int nt = (f >> 8) & 15;
        int mat = f >> 12;
        int hf = mat / 3, gate = mat % 3;
        int gg = lane >> 2, tg = lane & 3;
        int n_local = nt * 8 + gg;
        int k0 = ks * 16 + tg * 2;
        const float* W = hf ? Whh : Wih;
        const float* row = W + (size_t)(gate * 128 + n_local) * D;
        __half a0 = __float2half_rn(row[k0]);
        __half a1 = __float2half_rn(row[k0 + 1]);
        __half a2 = __float2half_rn(row[k0 + 8]);
        __half a3 = __float2half_rn(row[k0 + 9]);
        unsigned w0 = ((unsigned)__half_as_ushort(a1) << 16) | __half_as_ushort(a0);
        unsigned w1 = ((unsigned)__half_as_ushort(a3) << 16) | __half_as_ushort(a2);
        g_Bfrag[f] = make_uint2(w0, w1);
    }
}

// ---------------- fused: edge count + encoder stats (independent, block-partitioned) --
__global__ void count_enc_kernel(const int* __restrict__ ei, int E,
                                 const float* __restrict__ x, const float* __restrict__ Wenc,
                                 int N, int countBlocks) {
    if ((int)blockIdx.x < countBlocks) {
        int i = blockIdx.x * 256 + threadIdx.x;
        if (i < E) atomicAdd(&g_deg[ei[E + i]], 1);
    } else {
        int b = blockIdx.x - countBlocks;
        int d = threadIdx.x & 127;
        int half = threadIdx.x >> 7;
        float w0 = Wenc[d * 3], w1 = Wenc[d * 3 + 1], w2 = Wenc[d * 3 + 2];
        int n0 = b * 64 + half * 32;
        int lim = min(32, N - n0);
        float s = 0.f, sq = 0.f;
        for (int r = 0; r < lim; r++) {
            int n = n0 + r;
            float h = fmaf(x[n * 3], w0, fmaf(x[n * 3 + 1], w1, x[n * 3 + 2] * w2));
            s += h; sq += h * h;
        }
        if (lim > 0) {
            atomicAdd(&g_stats[d], s);
            atomicAdd(&g_stats[D + d], sq);
        }
    }
}

__global__ void __launch_bounds__(1024) scan_kernel(int N) {
    __shared__ int s[1024];
    int tid = threadIdx.x;
    int chunk = (N + 1023) / 1024;
    int start = tid * chunk;
    int end = min(start + chunk, N);
    int sum = 0;
    for (int i = start; i < end; i++) sum += g_deg[i];
    s[tid] = sum;
    __syncthreads();
    for (int off = 1; off < 1024; off <<= 1) {
        int v = (tid >= off) ? s[tid - off] : 0;
        __syncthreads();
        s[tid] += v;
        __syncthreads();
    }
    int run = (tid == 0) ? 0 : s[tid - 1];
    for (int i = start; i < end; i++) {
        g_off[i] = run;
        g_pos[i] = run;
        run += g_deg[i];
    }
    if (end == N && start <= N) g_off[N] = run;
}

// ---------------- fused: CSR fill + encoder apply (independent, block-partitioned) ----
__global__ void fill_apply_kernel(const int* __restrict__ ei, const float* __restrict__ norm, int E,
                                  const float* __restrict__ x, const float* __restrict__ Wenc,
                                  const float* __restrict__ gamma, const float* __restrict__ beta,
                                  int N, int fillBlocks) {
    if ((int)blockIdx.x < fillBlocks) {
        int i = blockIdx.x * 256 + threadIdx.x;
        if (i < E) {
            int t = ei[E + i];
            int p = atomicAdd(&g_pos[t], 1);
            g_edge[p] = make_uint2((unsigned)ei[i], __float_as_uint(norm[i]));
        }
    } else {
        int b = blockIdx.x - fillBlocks;
        int d = threadIdx.x & 127;
        int half = threadIdx.x >> 7;
        float w0 = Wenc[d * 3], w1 = Wenc[d * 3 + 1], w2 = Wenc[d * 3 + 2];
        float invN = 1.f / (float)N;
        float mu = g_stats[d] * invN;
        float var = g_stats[D + d] * invN - mu * mu;
        float rs = rsqrtf(var + 1e-5f);
        float ga = gamma[d] * rs, be = beta[d] - mu * ga;
        int n0 = b * 64 + half * 32;
        int lim = min(32, N - n0);
        for (int r = 0; r < lim; r++) {
            int n = n0 + r;
            float h = fmaf(x[n * 3], w0, fmaf(x[n * 3 + 1], w1, x[n * 3 + 2] * w2));
            float v = fmaf(h, ga, be);
            v = v > 0.f ? v : 0.f;
            g_prevA[(size_t)n * D + d] = v;
            g_hsum[(size_t)n * D + d] = v;
        }
    }
}

// ---------------- fused layer: gather + GRU (fp16 2-term), 16-col chunks, 3 CTAs/SM ---
#define PITCH 68
#define GROWS 64
#define ABUF  (GROWS * PITCH)
#define GRU_SMEM (4 * ABUF * 4 + 512 * 4)

__global__ void __launch_bounds__(256, 3) layer_kernel(const float* __restrict__ prev_in,
                                                       float* __restrict__ prev_out, int N) {
    extern __shared__ unsigned char smraw[];
    unsigned* sA = (unsigned*)smraw;
    float* sbias = (float*)(smraw + 4 * ABUF * 4);
    int tid = threadIdx.x;
    int n0 = blockIdx.x * GROWS;
    int lane = tid & 31, wid = tid >> 5;

#pragma unroll
    for (int t = 0; t < 2; t++) sbias[t * 256 + tid] = g_bias[t * 256 + tid];

    // --- fused gather + convert: warp w handles rows [w*8, w*8+8); reads prev_in only ---
    const float4* prev4 = (const float4*)prev_in;
#pragma unroll 1
    for (int rr = 0; rr < 8; rr++) {
        int rloc = wid * 8 + rr;
        int row = n0 + rloc;
        float4 acc = make_float4(0.f, 0.f, 0.f, 0.f);
        float4 hv = make_float4(0.f, 0.f, 0.f, 0.f);
        if (row < N) {
            int beg = g_off[row], end = g_off[row + 1];
            int j = beg;
            for (; j + 3 < end; j += 4) {
                uint2 e0 = g_edge[j], e1 = g_edge[j + 1], e2 = g_edge[j + 2], e3 = g_edge[j + 3];
                float4 v0 = prev4[(size_t)e0.x * 32 + lane];
                float4 v1 = prev4[(size_t)e1.x * 32 + lane];
                float4 v2 = prev4[(size_t)e2.x * 32 + lane];
                float4 v3 = prev4[(size_t)e3.x * 32 + lane];
                float n0v = __uint_as_float(e0.y), n1v = __uint_as_float(e1.y);
                float n2v = __uint_as_float(e2.y), n3v = __uint_as_float(e3.y);
                acc.x = fmaf(n0v, v0.x, fmaf(n1v, v1.x, fmaf(n2v, v2.x, fmaf(n3v, v3.x, acc.x))));
                acc.y = fmaf(n0v, v0.y, fmaf(n1v, v1.y, fmaf(n2v, v2.y, fmaf(n3v, v3.y, acc.y))));
                acc.z = fmaf(n0v, v0.z, fmaf(n1v, v1.z, fmaf(n2v, v2.z, fmaf(n3v, v3.z, acc.z))));
                acc.w = fmaf(n0v, v0.w, fmaf(n1v, v1.w, fmaf(n2v, v2.w, fmaf(n3v, v3.w, acc.w))));
            }
            for (; j < end; j++) {
                uint2 e0 = g_edge[j];
                float4 v0 = prev4[(size_t)e0.x * 32 + lane];
                float nv = __uint_as_float(e0.y);
                acc.x = fmaf(nv, v0.x, acc.x);
                acc.y = fmaf(nv, v0.y, acc.y);
                acc.z = fmaf(nv, v0.z, acc.z);
                acc.w = fmaf(nv, v0.w, acc.w);
            }
            hv = prev4[(size_t)row * 32 + lane];
            float4 sv = ((const float4*)g_hsum)[(size_t)row * 32 + lane];
            ((float4*)g_hsum)[(size_t)row * 32 + lane] =
                make_float4(sv.x + acc.x, sv.y + acc.y, sv.z + acc.z, sv.w + acc.w);
        }
        unsigned base = rloc * PITCH + lane * 2;
        unsigned lo, hi;
        hi = pack_hi_lo_f16(acc.x, acc.y, lo);
        sA[base] = hi; sA[ABUF + base] = lo;
        hi = pack_hi_lo_f16(acc.z, acc.w, lo);
        sA[base + 1] = hi; sA[ABUF + base + 1] = lo;
        hi = pack_hi_lo_f16(hv.x, hv.y, lo);
        sA[2 * ABUF + base] = hi; sA[3 * ABUF + base] = lo;
        hi = pack_hi_lo_f16(hv.z, hv.w, lo);
        sA[2 * ABUF + base + 1] = hi; sA[3 * ABUF + base + 1] = lo;
    }
    __syncthreads();

    int gg = lane >> 2, tg = lane & 3;
    int m0 = (wid & 3) * 16;
    int cg = wid >> 2;               // col group: chunks [cg*4, cg*4+4)
    const uint2* Bf = g_Bfrag;

#pragma unroll 1
    for (int ci = 0; ci < 4; ci++) {
        int chunk = cg * 4 + ci;     // 16 d-cols per chunk
        float aR[2][4], aZ[2][4], aN[2][4], aH[2][4];
#pragma unroll
        for (int nt = 0; nt < 2; nt++)
#pragma unroll
            for (int q = 0; q < 4; q++) { aR[nt][q] = 0.f; aZ[nt][q] = 0.f; aN[nt][q] = 0.f; aH[nt][q] = 0.f; }

#pragma unroll
        for (int hf = 0; hf < 2; hf++) {
            int bh_ = (hf * 2) * ABUF;
            int bl_ = (hf * 2 + 1) * ABUF;
#pragma unroll 2
            for (int ks = 0; ks < 8; ks++) {
                int kw = ks * 8 + tg;
                int rr = m0 + gg;
                unsigned Ah[4], Al[4];
                Ah[0] = sA[bh_ + rr * PITCH + kw];
                Ah[1] = sA[bh_ + (rr + 8) * PITCH + kw];
                Ah[2] = sA[bh_ + rr * PITCH + kw + 4];
                Ah[3] = sA[bh_ + (rr + 8) * PITCH + kw + 4];
                Al[0] = sA[bl_ + rr * PITCH + kw];
                Al[1] = sA[bl_ + (rr + 8) * PITCH + kw];
                Al[2] = sA[bl_ + rr * PITCH + kw + 4];
                Al[3] = sA[bl_ + (rr + 8) * PITCH + kw + 4];
                const uint2* bp = Bf + hf * 3 * 4096 + (chunk * 2) * 256 + ks * 32 + lane;
                uint2 b00 = bp[0 * 4096 + 0 * 256];
                uint2 b01 = bp[1 * 4096 + 0 * 256];
                uint2 b02 = bp[2 * 4096 + 0 * 256];
                uint2 b10 = bp[0 * 4096 + 1 * 256];
                uint2 b11 = bp[1 * 4096 + 1 * 256];
                uint2 b12 = bp[2 * 4096 + 1 * 256];
                float (*AN_)[4] = hf ? aH : aN;
                mma16816(aR[0], Ah, b00.x, b00.y);
                mma16816(aZ[0], Ah, b01.x, b01.y);
                mma16816(AN_[0], Ah, b02.x, b02.y);
                mma16816(aR[1], Ah, b10.x, b10.y);
                mma16816(aZ[1], Ah, b11.x, b11.y);
                mma16816(AN_[1], Ah, b12.x, b12.y);
                mma16816(aR[0], Al, b00.x, b00.y);
                mma16816(aZ[0], Al, b01.x, b01.y);
                mma16816(AN_[0], Al, b02.x, b02.y);
                mma16816(aR[1], Al, b10.x, b10.y);
                mma16816(aZ[1], Al, b11.x, b11.y);
                mma16816(AN_[1], Al, b12.x, b12.y);
            }
        }

        // epilogue for this chunk's 16 columns
#pragma unroll
        for (int nt = 0; nt < 2; nt++) {
#pragma unroll
            for (int rh = 0; rh < 2; rh++) {
                int rloc = m0 + rh * 8 + gg;
                int row = n0 + rloc;
                if (row < N) {
                    int col = chunk * 16 + nt * 8 + tg * 2;
                    int i0 = rh * 2;
                    float rv0 = aR[nt][i0]     + sbias[col];
                    float rv1 = aR[nt][i0 + 1] + sbias[col + 1];
                    float zv0 = aZ[nt][i0]     + sbias[128 + col];
                    float zv1 = aZ[nt][i0 + 1] + sbias[128 + col + 1];
                    float in0 = aN[nt][i0]     + sbias[256 + col];
                    float in1 = aN[nt][i0 + 1] + sbias[256 + col + 1];
                    float hn0 = aH[nt][i0]     + sbias[384 + col];
                    float hn1 = aH[nt][i0 + 1] + sbias[384 + col + 1];
                    int cw = col >> 1;
                    unsigned wh = sA[2 * ABUF + rloc * PITCH + cw];
                    unsigned wl = sA[3 * ABUF + rloc * PITCH + cw];
                    float2 fh = __half22float2(*(__half2*)&wh);
                    float2 fl = __half22float2(*(__half2*)&wl);
                    float hp0 = fh.x + fl.x, hp1 = fh.y + fl.y;
                    float rg0 = fast_sigmoid(rv0);
                    float rg1 = fast_sigmoid(rv1);
                    float zg0 = fast_sigmoid(zv0);
                    float zg1 = fast_sigmoid(zv1);
                    float ng0 = fast_tanh(fmaf(rg0, hn0, in0));
                    float ng1 = fast_tanh(fmaf(rg1, hn1, in1));
                    float o0 = fmaf(zg0, hp0 - ng0, ng0);
                    float o1 = fmaf(zg1, hp1 - ng1, ng1);
                    *(float2*)(prev_out + (size_t)row * D + col) = make_float2(o0, o1);
                }
            }
        }
    }
}

// ---------------- decode (128 threads: two 16-row halves) -----------------------------
__global__ void __launch_bounds__(128) dec1_kernel(int N) {
    __shared__ float s_z[DEC_ROWS * D];
    int tid = threadIdx.x;
    int j = tid & 63;
    int half = tid >> 6;
    int n0 = blockIdx.x * DEC_ROWS;
    const float inv6 = 1.f / 6.f;
    for (int i = tid; i < DEC_ROWS * D; i += 128) {
        int n = n0 + i / D;
        s_z[i] = (n < N) ? g_hsum[(size_t)n0 * D + i] * inv6 : 0.f;
    }
    __syncthreads();
    float acc[16];
#pragma unroll
    for (int r = 0; r < 16; r++) acc[r] = 0.f;
    int r0 = half * 16;
#pragma unroll 2
    for (int k = 0; k < D; k++) {
        float w = g_WTd[k * (D / 2) + j];
#pragma unroll
        for (int r = 0; r < 16; r++) acc[r] = fmaf(w, s_z[(r0 + r) * D + k], acc[r]);
    }
    float s = 0.f, sq = 0.f;
#pragma unroll
    for (int r = 0; r < 16; r++) {
        int n = n0 + r0 + r;
        if (n < N) {
            g_y0[(size_t)n * (D / 2) + j] = acc[r];
            s += acc[r]; sq += acc[r] * acc[r];
        }
    }
    atomicAdd(&g_stats[2 * D + j], s);
    atomicAdd(&g_stats[2 * D + (D / 2) + j], sq);
}

__global__ void dec2_kernel(const float* __restrict__ gamma, const float* __restrict__ beta,
                            const float* __restrict__ W2, float* __restrict__ out, int N) {
    int warp = (blockIdx.x * blockDim.x + threadIdx.x) >> 5;
    int lane = threadIdx.x & 31;
    if (warp >= N) return;
    float invN = 1.f / (float)N;
    float acc = 0.f;
#pragma unroll
    for (int t = 0; t < 2; t++) {
        int jj = lane + t * 32;
        float mu = g_stats[2 * D + jj] * invN;
        float var = g_stats[2 * D + (D / 2) + jj] * invN - mu * mu;
        float rs = rsqrtf(var + 1e-5f);
        float v = (g_y0[(size_t)warp * (D / 2) + jj] - mu) * rs * gamma[jj] + beta[jj];
        v = v > 0.f ? v : 0.f;
        acc = fmaf(v, W2[jj], acc);
    }
#pragma unroll
    for (int o = 16; o > 0; o >>= 1) acc += __shfl_down_sync(0xffffffffu, acc, o);
    if (lane == 0) out[warp] = acc;
}

// ---------------- launch ----------------------------------------------------------------
extern "C" void kernel_launch(void* const* d_in, const int* in_sizes, int n_in,
                              void* d_out, int out_size) {
    const float* x    = (const float*)d_in[0];
    const int*   ei   = (const int*)d_in[1];
    const float* norm = (const float*)d_in[2];
    const float* Wenc = (const float*)d_in[3];
    const float* beg  = (const float*)d_in[4];
    const float* beb  = (const float*)d_in[5];
    const float* Wih  = (const float*)d_in[6];
    const float* Whh  = (const float*)d_in[7];
    const float* bih  = (const float*)d_in[8];
    const float* bhh  = (const float*)d_in[9];
    const float* Wdec = (const float*)d_in[10];
    const float* bdg  = (const float*)d_in[11];
    const float* bdb  = (const float*)d_in[12];
    const float* W2   = (const float*)d_in[13];

    int N = in_sizes[0] / 3;
    int E = in_sizes[2];
    float* out = (float*)d_out;

    cudaFuncSetAttribute(layer_kernel, cudaFuncAttributeMaxDynamicSharedMemorySize, GRU_SMEM);

    prep_kernel<<<192, 256>>>(Wih, Whh, bih, bhh, Wdec, N);

    int cb = (E + 255) / 256;         // count blocks
    int eb = (N + 63) / 64;           // encoder blocks (64 rows each, 256 threads)
    count_enc_kernel<<<cb + eb, 256>>>(ei, E, x, Wenc, N, cb);

    scan_kernel<<<1, 1024>>>(N);

    fill_apply_kernel<<<cb + eb, 256>>>(ei, norm, E, x, Wenc, beg, beb, N, cb);

    float* pA = nullptr;
    float* pB = nullptr;
    cudaGetSymbolAddress((void**)&pA, g_prevA);
    cudaGetSymbolAddress((void**)&pB, g_prevB);

    int gb = (N + GROWS - 1) / GROWS;
    for (int L = 0; L < 5; L++) {
        const float* pin  = (L & 1) ? pB : pA;
        float*       pout = (L & 1) ? pA : pB;
        layer_kernel<<<gb, 256, GRU_SMEM>>>(pin, pout, N);
    }

    dec1_kernel<<<(N + DEC_ROWS - 1) / DEC_ROWS, 128>>>(N);

    long long d2threads = (long long)N * 32;
    dec2_kernel<<<(int)((d2threads + 255) / 256), 256>>>(bdg, bdb, W2, out, N);
}

// round 17
// speedup vs baseline: 1.1601x; 1.1086x over previous
#include <cuda_runtime.h>
#include <cuda_fp16.h>
#include <math.h>

#define D 128
#define NMAX 50000
#define EMAX 640000
#define DEC_ROWS 32

// ---------------- scratch globals ------------------------------------------------
__device__ __align__(16) float g_prevA[NMAX * D];
__device__ __align__(16) float g_prevB[NMAX * D];
__device__ __align__(16) float g_hsum[NMAX * D];
__device__ __align__(16) float g_y0[NMAX * (D / 2)];
__device__ __align__(16) float g_stats[2 * D + 2 * (D / 2)];
__device__ __align__(16) float g_WTd[D * (D / 2)];
__device__ __align__(16) float g_bias[512];
// B fragments (single fp16): [mat(6: hf*3+gate)][ntile(16)][kstep(8)][lane(32)] -> uint2 {b0,b1}
__device__ __align__(16) uint2 g_Bfrag[6 * 4096];
// CSR-by-dst
__device__ __align__(16) int  g_deg[NMAX];
__device__ __align__(16) int  g_off[NMAX + 1];
__device__ __align__(16) int  g_pos[NMAX];
__device__ __align__(16) uint2 g_edge[EMAX];   // {src, norm_bits}

__device__ __forceinline__ unsigned pack_hi_lo_f16(float x0, float x1, unsigned& lop) {
    __half h0 = __float2half_rn(x0), h1 = __float2half_rn(x1);
    float l0 = x0 - __half2float(h0), l1 = x1 - __half2float(h1);
    __half g0 = __float2half_rn(l0), g1 = __float2half_rn(l1);
    lop = ((unsigned)__half_as_ushort(g1) << 16) | __half_as_ushort(g0);
    return ((unsigned)__half_as_ushort(h1) << 16) | __half_as_ushort(h0);
}

__device__ __forceinline__ void mma16816(float* c, const unsigned* a, unsigned b0, unsigned b1) {
    asm("mma.sync.aligned.m16n8k16.row.col.f32.f16.f16.f32 "
        "{%0,%1,%2,%3}, {%4,%5,%6,%7}, {%8,%9}, {%0,%1,%2,%3};"
        : "+f"(c[0]), "+f"(c[1]), "+f"(c[2]), "+f"(c[3])
        : "r"(a[0]), "r"(a[1]), "r"(a[2]), "r"(a[3]), "r"(b0), "r"(b1));
}

__device__ __forceinline__ float fast_sigmoid(float x) {
    return __fdividef(1.f, 1.f + __expf(-x));
}
__device__ __forceinline__ float fast_tanh(float x) {
    float e = __expf(2.f * x);
    return 1.f - __fdividef(2.f, e + 1.f);
}

// ---------------- prep ------------------------------------------------------------
__global__ void prep_kernel(const float* __restrict__ Wih, const float* __restrict__ Whh,
                            const float* __restrict__ bih, const float* __restrict__ bhh,
                            const float* __restrict__ Wdec, int N) {
    int i = blockIdx.x * blockDim.x + threadIdx.x;
    int stride = gridDim.x * blockDim.x;
    if (i < 384) g_stats[i] = 0.f;
    if (i < 256) g_bias[i] = bih[i] + bhh[i];
    else if (i < 384) g_bias[i] = bih[i];
    if (i >= 384 && i < 512) g_bias[i] = bhh[i - 128];
    for (int idx = i; idx < N; idx += stride) g_deg[idx] = 0;
    for (int idx = i; idx < D * (D / 2); idx += stride) {
        int k = idx / (D / 2), j = idx % (D / 2);
        g_WTd[idx] = Wdec[j * D + k];
    }
    for (int f = i; f < 6 * 4096; f += stride) {
        int lane = f & 31;
        int ks = (f >> 5) & 7;
        int nt = (f >> 8) & 15;
        int mat = f >> 12;
        int hf = mat / 3, gate = mat % 3;
        int gg = lane >> 2, tg = lane & 3;
        int n_local = nt * 8 + gg;
        int k0 = ks * 16 + tg * 2;
        const float* W = hf ? Whh : Wih;
        const float* row = W + (size_t)(gate * 128 + n_local) * D;
        __half a0 = __float2half_rn(row[k0]);
        __half a1 = __float2half_rn(row[k0 + 1]);
        __half a2 = __float2half_rn(row[k0 + 8]);
        __half a3 = __float2half_rn(row[k0 + 9]);
        unsigned w0 = ((unsigned)__half_as_ushort(a1) << 16) | __half_as_ushort(a0);
        unsigned w1 = ((unsigned)__half_as_ushort(a3) << 16) | __half_as_ushort(a2);
        g_Bfrag[f] = make_uint2(w0, w1);
    }
}

// ---------------- fused: edge count + encoder stats ----------------------------------
__global__ void count_enc_kernel(const int* __restrict__ ei, int E,
                                 const float* __restrict__ x, const float* __restrict__ Wenc,
                                 int N, int countBlocks) {
    if ((int)blockIdx.x < countBlocks) {
        int i = blockIdx.x * 256 + threadIdx.x;
        if (i < E) atomicAdd(&g_deg[ei[E + i]], 1);
    } else {
        int b = blockIdx.x - countBlocks;
        int d = threadIdx.x & 127;
        int half = threadIdx.x >> 7;
        float w0 = Wenc[d * 3], w1 = Wenc[d * 3 + 1], w2 = Wenc[d * 3 + 2];
        int n0 = b * 64 + half * 32;
        int lim = min(32, N - n0);
        float s = 0.f, sq = 0.f;
        for (int r = 0; r < lim; r++) {
            int n = n0 + r;
            float h = fmaf(x[n * 3], w0, fmaf(x[n * 3 + 1], w1, x[n * 3 + 2] * w2));
            s += h; sq += h * h;
        }
        if (lim > 0) {
            atomicAdd(&g_stats[d], s);
            atomicAdd(&g_stats[D + d], sq);
        }
    }
}

__global__ void __launch_bounds__(1024) scan_kernel(int N) {
    __shared__ int s[1024];
    int tid = threadIdx.x;
    int chunk = (N + 1023) / 1024;
    int start = tid * chunk;
    int end = min(start + chunk, N);
    int sum = 0;
    for (int i = start; i < end; i++) sum += g_deg[i];
    s[tid] = sum;
    __syncthreads();
    for (int off = 1; off < 1024; off <<= 1) {
        int v = (tid >= off) ? s[tid - off] : 0;
        __syncthreads();
        s[tid] += v;
        __syncthreads();
    }
    int run = (tid == 0) ? 0 : s[tid - 1];
    for (int i = start; i < end; i++) {
        g_off[i] = run;
        g_pos[i] = run;
        run += g_deg[i];
    }
    if (end == N && start <= N) g_off[N] = run;
}

// ---------------- fused: CSR fill + encoder apply -------------------------------------
__global__ void fill_apply_kernel(const int* __restrict__ ei, const float* __restrict__ norm, int E,
                                  const float* __restrict__ x, const float* __restrict__ Wenc,
                                  const float* __restrict__ gamma, const float* __restrict__ beta,
                                  int N, int fillBlocks) {
    if ((int)blockIdx.x < fillBlocks) {
        int i = blockIdx.x * 256 + threadIdx.x;
        if (i < E) {
            int t = ei[E + i];
            int p = atomicAdd(&g_pos[t], 1);
            g_edge[p] = make_uint2((unsigned)ei[i], __float_as_uint(norm[i]));
        }
    } else {
        int b = blockIdx.x - fillBlocks;
        int d = threadIdx.x & 127;
        int half = threadIdx.x >> 7;
        float w0 = Wenc[d * 3], w1 = Wenc[d * 3 + 1], w2 = Wenc[d * 3 + 2];
        float invN = 1.f / (float)N;
        float mu = g_stats[d] * invN;
        float var = g_stats[D + d] * invN - mu * mu;
        float rs = rsqrtf(var + 1e-5f);
        float ga = gamma[d] * rs, be = beta[d] - mu * ga;
        int n0 = b * 64 + half * 32;
        int lim = min(32, N - n0);
        for (int r = 0; r < lim; r++) {
            int n = n0 + r;
            float h = fmaf(x[n * 3], w0, fmaf(x[n * 3 + 1], w1, x[n * 3 + 2] * w2));
            float v = fmaf(h, ga, be);
            v = v > 0.f ? v : 0.f;
            g_prevA[(size_t)n * D + d] = v;
            g_hsum[(size_t)n * D + d] = v;
        }
    }
}

// ---------------- fused layer: gather + GRU (single fp16 term), 3 CTAs/SM -------------
#define PITCH 68
#define GROWS 64
#define ABUF  (GROWS * PITCH)
#define GRU_SMEM (4 * ABUF * 4 + 512 * 4)

__global__ void __launch_bounds__(256, 3) layer_kernel(const float* __restrict__ prev_in,
                                                       float* __restrict__ prev_out, int N) {
    extern __shared__ unsigned char smraw[];
    unsigned* sA = (unsigned*)smraw;
    float* sbias = (float*)(smraw + 4 * ABUF * 4);
    int tid = threadIdx.x;
    int n0 = blockIdx.x * GROWS;
    int lane = tid & 31, wid = tid >> 5;

#pragma unroll
    for (int t = 0; t < 2; t++) sbias[t * 256 + tid] = g_bias[t * 256 + tid];

    // --- fused gather + convert: warp w handles rows [w*8, w*8+8); reads prev_in only ---
    const float4* prev4 = (const float4*)prev_in;
#pragma unroll 1
    for (int rr = 0; rr < 8; rr++) {
        int rloc = wid * 8 + rr;
        int row = n0 + rloc;
        float4 acc = make_float4(0.f, 0.f, 0.f, 0.f);
        float4 hv = make_float4(0.f, 0.f, 0.f, 0.f);
        if (row < N) {
            int beg = g_off[row], end = g_off[row + 1];
            int j = beg;
            for (; j + 3 < end; j += 4) {
                uint2 e0 = g_edge[j], e1 = g_edge[j + 1], e2 = g_edge[j + 2], e3 = g_edge[j + 3];
                float4 v0 = prev4[(size_t)e0.x * 32 + lane];
                float4 v1 = prev4[(size_t)e1.x * 32 + lane];
                float4 v2 = prev4[(size_t)e2.x * 32 + lane];
                float4 v3 = prev4[(size_t)e3.x * 32 + lane];
                float n0v = __uint_as_float(e0.y), n1v = __uint_as_float(e1.y);
                float n2v = __uint_as_float(e2.y), n3v = __uint_as_float(e3.y);
                acc.x = fmaf(n0v, v0.x, fmaf(n1v, v1.x, fmaf(n2v, v2.x, fmaf(n3v, v3.x, acc.x))));
                acc.y = fmaf(n0v, v0.y, fmaf(n1v, v1.y, fmaf(n2v, v2.y, fmaf(n3v, v3.y, acc.y))));
                acc.z = fmaf(n0v, v0.z, fmaf(n1v, v1.z, fmaf(n2v, v2.z, fmaf(n3v, v3.z, acc.z))));
                acc.w = fmaf(n0v, v0.w, fmaf(n1v, v1.w, fmaf(n2v, v2.w, fmaf(n3v, v3.w, acc.w))));
            }
            for (; j < end; j++) {
                uint2 e0 = g_edge[j];
                float4 v0 = prev4[(size_t)e0.x * 32 + lane];
                float nv = __uint_as_float(e0.y);
                acc.x = fmaf(nv, v0.x, acc.x);
                acc.y = fmaf(nv, v0.y, acc.y);
                acc.z = fmaf(nv, v0.z, acc.z);
                acc.w = fmaf(nv, v0.w, acc.w);
            }
            hv = prev4[(size_t)row * 32 + lane];
            float4 sv = ((const float4*)g_hsum)[(size_t)row * 32 + lane];
            ((float4*)g_hsum)[(size_t)row * 32 + lane] =
                make_float4(sv.x + acc.x, sv.y + acc.y, sv.z + acc.z, sv.w + acc.w);
        }
        unsigned base = rloc * PITCH + lane * 2;
        unsigned lo, hi;
        // agg: hi only (single-term MMA input)
        hi = pack_hi_lo_f16(acc.x, acc.y, lo);
        sA[base] = hi;
        hi = pack_hi_lo_f16(acc.z, acc.w, lo);
        sA[base + 1] = hi;
        // prev: hi for MMA, hi+lo kept for full-precision h_prev reconstruction in epilogue
        hi = pack_hi_lo_f16(hv.x, hv.y, lo);
        sA[2 * ABUF + base] = hi; sA[3 * ABUF + base] = lo;
        hi = pack_hi_lo_f16(hv.z, hv.w, lo);
        sA[2 * ABUF + base + 1] = hi; sA[3 * ABUF + base + 1] = lo;
    }
    __syncthreads();

    int gg = lane >> 2, tg = lane & 3;
    int m0 = (wid & 3) * 16;
    int cg = wid >> 2;               // col group: chunks [cg*4, cg*4+4)
    const uint2* Bf = g_Bfrag;

#pragma unroll 1
    for (int ci = 0; ci < 4; ci++) {
        int chunk = cg * 4 + ci;     // 16 d-cols per chunk
        float aR[2][4], aZ[2][4], aN[2][4], aH[2][4];
#pragma unroll
        for (int nt = 0; nt < 2; nt++)
#pragma unroll
            for (int q = 0; q < 4; q++) { aR[nt][q] = 0.f; aZ[nt][q] = 0.f; aN[nt][q] = 0.f; aH[nt][q] = 0.f; }

#pragma unroll
        for (int hf = 0; hf < 2; hf++) {
            int bh_ = (hf == 0) ? 0 : 2 * ABUF;    // agg-hi buffer or prev-hi buffer
#pragma unroll 2
            for (int ks = 0; ks < 8; ks++) {
                int kw = ks * 8 + tg;
                int rr = m0 + gg;
                unsigned Ah[4];
                Ah[0] = sA[bh_ + rr * PITCH + kw];
                Ah[1] = sA[bh_ + (rr + 8) * PITCH + kw];
                Ah[2] = sA[bh_ + rr * PITCH + kw + 4];
                Ah[3] = sA[bh_ + (rr + 8) * PITCH + kw + 4];
                const uint2* bp = Bf + hf * 3 * 4096 + (chunk * 2) * 256 + ks * 32 + lane;
                uint2 b00 = bp[0 * 4096 + 0 * 256];
                uint2 b01 = bp[1 * 4096 + 0 * 256];
                uint2 b02 = bp[2 * 4096 + 0 * 256];
                uint2 b10 = bp[0 * 4096 + 1 * 256];
                uint2 b11 = bp[1 * 4096 + 1 * 256];
                uint2 b12 = bp[2 * 4096 + 1 * 256];
                float (*AN_)[4] = hf ? aH : aN;
                mma16816(aR[0], Ah, b00.x, b00.y);
                mma16816(aZ[0], Ah, b01.x, b01.y);
                mma16816(AN_[0], Ah, b02.x, b02.y);
                mma16816(aR[1], Ah, b10.x, b10.y);
                mma16816(aZ[1], Ah, b11.x, b11.y);
                mma16816(AN_[1], Ah, b12.x, b12.y);
            }
        }

        // epilogue for this chunk's 16 columns
#pragma unroll
        for (int nt = 0; nt < 2; nt++) {
#pragma unroll
            for (int rh = 0; rh < 2; rh++) {
                int rloc = m0 + rh * 8 + gg;
                int row = n0 + rloc;
                if (row < N) {
                    int col = chunk * 16 + nt * 8 + tg * 2;
                    int i0 = rh * 2;
                    float rv0 = aR[nt][i0]     + sbias[col];
                    float rv1 = aR[nt][i0 + 1] + sbias[col + 1];
                    float zv0 = aZ[nt][i0]     + sbias[128 + col];
                    float zv1 = aZ[nt][i0 + 1] + sbias[128 + col + 1];
                    float in0 = aN[nt][i0]     + sbias[256 + col];
                    float in1 = aN[nt][i0 + 1] + sbias[256 + col + 1];
                    float hn0 = aH[nt][i0]     + sbias[384 + col];
                    float hn1 = aH[nt][i0 + 1] + sbias[384 + col + 1];
                    int cw = col >> 1;
                    unsigned wh = sA[2 * ABUF + rloc * PITCH + cw];
                    unsigned wl = sA[3 * ABUF + rloc * PITCH + cw];
                    float2 fh = __half22float2(*(__half2*)&wh);
                    float2 fl = __half22float2(*(__half2*)&wl);
                    float hp0 = fh.x + fl.x, hp1 = fh.y + fl.y;
                    float rg0 = fast_sigmoid(rv0);
                    float rg1 = fast_sigmoid(rv1);
                    float zg0 = fast_sigmoid(zv0);
                    float zg1 = fast_sigmoid(zv1);
                    float ng0 = fast_tanh(fmaf(rg0, hn0, in0));
                    float ng1 = fast_tanh(fmaf(rg1, hn1, in1));
                    float o0 = fmaf(zg0, hp0 - ng0, ng0);
                    float o1 = fmaf(zg1, hp1 - ng1, ng1);
                    *(float2*)(prev_out + (size_t)row * D + col) = make_float2(o0, o1);
                }
            }
        }
    }
}

// ---------------- decode (128 threads: two 16-row halves) -----------------------------
__global__ void __launch_bounds__(128) dec1_kernel(int N) {
    __shared__ float s_z[DEC_ROWS * D];
    int tid = threadIdx.x;
    int j = tid & 63;
    int half = tid >> 6;
    int n0 = blockIdx.x * DEC_ROWS;
    const float inv6 = 1.f / 6.f;
    for (int i = tid; i < DEC_ROWS * D; i += 128) {
        int n = n0 + i / D;
        s_z[i] = (n < N) ? g_hsum[(size_t)n0 * D + i] * inv6 : 0.f;
    }
    __syncthreads();
    float acc[16];
#pragma unroll
    for (int r = 0; r < 16; r++) acc[r] = 0.f;
    int r0 = half * 16;
#pragma unroll 2
    for (int k = 0; k < D; k++) {
        float w = g_WTd[k * (D / 2) + j];
#pragma unroll
        for (int r = 0; r < 16; r++) acc[r] = fmaf(w, s_z[(r0 + r) * D + k], acc[r]);
    }
    float s = 0.f, sq = 0.f;
#pragma unroll
    for (int r = 0; r < 16; r++) {
        int n = n0 + r0 + r;
        if (n < N) {
            g_y0[(size_t)n * (D / 2) + j] = acc[r];
            s += acc[r]; sq += acc[r] * acc[r];
        }
    }
    atomicAdd(&g_stats[2 * D + j], s);
    atomicAdd(&g_stats[2 * D + (D / 2) + j], sq);
}

__global__ void dec2_kernel(const float* __restrict__ gamma, const float* __restrict__ beta,
                            const float* __restrict__ W2, float* __restrict__ out, int N) {
    int warp = (blockIdx.x * blockDim.x + threadIdx.x) >> 5;
    int lane = threadIdx.x & 31;
    if (warp >= N) return;
    float invN = 1.f / (float)N;
    float acc = 0.f;
#pragma unroll
    for (int t = 0; t < 2; t++) {
        int jj = lane + t * 32;
        float mu = g_stats[2 * D + jj] * invN;
        float var = g_stats[2 * D + (D / 2) + jj] * invN - mu * mu;
        float rs = rsqrtf(var + 1e-5f);
        float v = (g_y0[(size_t)warp * (D / 2) + jj] - mu) * rs * gamma[jj] + beta[jj];
        v = v > 0.f ? v : 0.f;
        acc = fmaf(v, W2[jj], acc);
    }
#pragma unroll
    for (int o = 16; o > 0; o >>= 1) acc += __shfl_down_sync(0xffffffffu, acc, o);
    if (lane == 0) out[warp] = acc;
}

// ---------------- launch ----------------------------------------------------------------
extern "C" void kernel_launch(void* const* d_in, const int* in_sizes, int n_in,
                              void* d_out, int out_size) {
    const float* x    = (const float*)d_in[0];
    const int*   ei   = (const int*)d_in[1];
    const float* norm = (const float*)d_in[2];
    const float* Wenc = (const float*)d_in[3];
    const float* beg  = (const float*)d_in[4];
    const float* beb  = (const float*)d_in[5];
    const float* Wih  = (const float*)d_in[6];
    const float* Whh  = (const float*)d_in[7];
    const float* bih  = (const float*)d_in[8];
    const float* bhh  = (const float*)d_in[9];
    const float* Wdec = (const float*)d_in[10];
    const float* bdg  = (const float*)d_in[11];
    const float* bdb  = (const float*)d_in[12];
    const float* W2   = (const float*)d_in[13];

    int N = in_sizes[0] / 3;
    int E = in_sizes[2];
    float* out = (float*)d_out;

    cudaFuncSetAttribute(layer_kernel, cudaFuncAttributeMaxDynamicSharedMemorySize, GRU_SMEM);

    prep_kernel<<<192, 256>>>(Wih, Whh, bih, bhh, Wdec, N);

    int cb = (E + 255) / 256;
    int eb = (N + 63) / 64;
    count_enc_kernel<<<cb + eb, 256>>>(ei, E, x, Wenc, N, cb);

    scan_kernel<<<1, 1024>>>(N);

    fill_apply_kernel<<<cb + eb, 256>>>(ei, norm, E, x, Wenc, beg, beb, N, cb);

    float* pA = nullptr;
    float* pB = nullptr;
    cudaGetSymbolAddress((void**)&pA, g_prevA);
    cudaGetSymbolAddress((void**)&pB, g_prevB);

    int gb = (N + GROWS - 1) / GROWS;
    for (int L = 0; L < 5; L++) {
        const float* pin  = (L & 1) ? pB : pA;
        float*       pout = (L & 1) ? pA : pB;
        layer_kernel<<<gb, 256, GRU_SMEM>>>(pin, pout, N);
    }

    dec1_kernel<<<(N + DEC_ROWS - 1) / DEC_ROWS, 128>>>(N);

    long long d2threads = (long long)N * 32;
    dec2_kernel<<<(int)((d2threads + 255) / 256), 256>>>(bdg, bdb, W2, out, N);
}